// round 15
// baseline (speedup 1.0000x reference)
#include <cuda_runtime.h>
#include <cstdint>

// ---------------------------------------------------------------------------
// Gate_32375463478041 — R11 GEMM + PDL-overlapped spin epilogue
//   Kernel 1 (R11 champion, byte-identical schedule + PDL trigger):
//     CTA tile M=128/N=128, K-split 4, KB=64 chunks, warps 0-3 MMA (64x64),
//     warps 4-7 producers, 2-stage ring, 1 syncthreads/chunk.
//   Kernel 2 (launched with programmatic stream serialization): 32 CTAs,
//     one per batch; spins on per-batch arrival counter, then reduces
//     L2-hot partials + bias + softplus + top-2 + softmax.
// ---------------------------------------------------------------------------

#define KSPLIT 4
#define ROWS   4096
#define NCHUNK 32
#define TILE_B 32768            // 128 rows x 256B
#define STAGE_B (2*TILE_B)      // A tile + B tile = 64 KiB
#define SMEM_BYTES (2*STAGE_B)  // 128 KiB double buffer

__device__ float g_partial[KSPLIT * ROWS * 128];   // 8 MiB scratch
__device__ int   g_cnt[32];                        // zero-initialized

__device__ __forceinline__ uint32_t smem_u32(const void* p) {
    uint32_t a;
    asm("{ .reg .u64 t; cvta.to.shared.u64 t, %1; cvt.u32.u64 %0, t; }"
        : "=r"(a) : "l"(p));
    return a;
}

__device__ __forceinline__ void ldsm4(uint32_t* r, uint32_t addr) {
    asm volatile("ldmatrix.sync.aligned.m8n8.x4.shared.b16 {%0,%1,%2,%3}, [%4];"
                 : "=r"(r[0]), "=r"(r[1]), "=r"(r[2]), "=r"(r[3]) : "r"(addr));
}

__device__ __forceinline__ void mma16816(float* d, const uint32_t* a, const uint32_t* b) {
    asm volatile(
        "mma.sync.aligned.m16n8k16.row.col.f32.bf16.bf16.f32 "
        "{%0,%1,%2,%3}, {%4,%5,%6,%7}, {%8,%9}, {%0,%1,%2,%3};"
        : "+f"(d[0]), "+f"(d[1]), "+f"(d[2]), "+f"(d[3])
        : "r"(a[0]), "r"(a[1]), "r"(a[2]), "r"(a[3]), "r"(b[0]), "r"(b[1]));
}

__device__ __forceinline__ void split2(float f0, float f1, uint32_t& h, uint32_t& lo) {
    asm("cvt.rn.bf16x2.f32 %0, %1, %2;" : "=r"(h) : "f"(f1), "f"(f0));
    float r0 = f0 - __uint_as_float(h << 16);
    float r1 = f1 - __uint_as_float(h & 0xffff0000u);
    asm("cvt.rn.bf16x2.f32 %0, %1, %2;" : "=r"(lo) : "f"(r1), "f"(r0));
}

__device__ __forceinline__ float softplus_f(float v) {
    return fmaxf(v, 0.0f) + log1pf(expf(-fabsf(v)));
}

// ---------------------------------------------------------------------------
__global__ void __launch_bounds__(256, 1) gate_gemm_hmma(
    const float* __restrict__ x,
    const float* __restrict__ Wm,
    const float* __restrict__ Wn)
{
    extern __shared__ char smem[];
    const uint32_t sbase = smem_u32(smem);
    const int t = threadIdx.x;
    const int w = t >> 5;
    const int l = t & 31;
    const int b  = blockIdx.x;
    const int ks = blockIdx.y;

#if defined(__CUDA_ARCH__) && (__CUDA_ARCH__ >= 900)
    if (t == 0) cudaTriggerProgrammaticLaunchCompletion();
#endif

    if (w < 4) {
        // =================== MMA warps (0-3): 64x64 tile =====================
        const int wm = w & 1;
        const int wn = w >> 1;

        const int m_add = ((l >> 3) & 1) * 8 + (l & 7);
        const int kA2   = (l >> 4) * 16;
        const int xm    = (m_add & 7) * 16;
        const int n_add = (l & 7) + ((l >> 4) << 3);
        const int kB2   = ((l >> 3) & 1) * 16;
        const int xn    = (n_add & 7) * 16;

        uint32_t aRow[4], bRow[4];
#pragma unroll
        for (int i = 0; i < 4; i++) {
            aRow[i] = (uint32_t)(wm * 64 + i * 16 + m_add) * 256u;
            bRow[i] = (uint32_t)(wn * 64 + i * 16 + n_add) * 256u + TILE_B;
        }

        float acc[4][8][4];
#pragma unroll
        for (int i = 0; i < 4; i++)
#pragma unroll
            for (int j = 0; j < 8; j++)
#pragma unroll
                for (int q = 0; q < 4; q++) acc[i][j][q] = 0.0f;

        __syncthreads();   // wait for prologue fill of buffer 0

        for (int c = 0; c < NCHUNK; c++) {
            const uint32_t sb = sbase + (uint32_t)(c & 1) * STAGE_B;
            uint32_t AH[16], AL[16], BH[16], BL[16];
#pragma unroll
            for (int kk = 0; kk < 4; kk++) {
                const int koH = kk * 32;
#pragma unroll
                for (int mt = 0; mt < 4; mt++) {
                    ldsm4(AH + 4 * mt, sb + aRow[mt] + ((koH + kA2) ^ xm));
                    ldsm4(AL + 4 * mt, sb + aRow[mt] + 128u + ((koH + kA2) ^ xm));
                }
#pragma unroll
                for (int nt = 0; nt < 4; nt++) {
                    ldsm4(BH + 4 * nt, sb + bRow[nt] + ((koH + kB2) ^ xn));
                    ldsm4(BL + 4 * nt, sb + bRow[nt] + 128u + ((koH + kB2) ^ xn));
                }
#pragma unroll
                for (int mt = 0; mt < 4; mt++)
#pragma unroll
                    for (int nj = 0; nj < 8; nj++)
                        mma16816(acc[mt][nj], AH + 4 * mt, BH + 2 * nj);
#pragma unroll
                for (int mt = 0; mt < 4; mt++)
#pragma unroll
                    for (int nj = 0; nj < 8; nj++)
                        mma16816(acc[mt][nj], AH + 4 * mt, BL + 2 * nj);
#pragma unroll
                for (int mt = 0; mt < 4; mt++)
#pragma unroll
                    for (int nj = 0; nj < 8; nj++)
                        mma16816(acc[mt][nj], AL + 4 * mt, BH + 2 * nj);
            }
            __syncthreads();
        }

        // ---- write partials ----
#pragma unroll
        for (int mt = 0; mt < 4; mt++) {
            int row = b * 128 + wm * 64 + mt * 16 + (l >> 2);
#pragma unroll
            for (int nj = 0; nj < 8; nj++) {
                int col = wn * 64 + nj * 8 + 2 * (l & 3);
                size_t idx0 = ((size_t)ks * ROWS + row) * 128 + col;
                *(float2*)(g_partial + idx0)            = make_float2(acc[mt][nj][0], acc[mt][nj][1]);
                *(float2*)(g_partial + idx0 + 8 * 128)  = make_float2(acc[mt][nj][2], acc[mt][nj][3]);
            }
        }
    } else {
        // =================== producer warps (4-7) ============================
        const int p = t - 128;
        const uint32_t rowA = (uint32_t)p * 256u;
        const uint32_t rowB = (uint32_t)p * 256u + TILE_B;
        const int xp7 = (p & 7) * 16;

        const float2* xg = (const float2*)x + (size_t)b * 524288u
                                            + (size_t)ks * 131072u + p;
        const float* wbase = (p < 64) ? (Wm + (size_t)p * 8192u)
                                      : (Wn + (size_t)(p - 64) * 8192u);
        const float4* wq = (const float4*)(wbase + ks * 2048);

        float2 xs[32]; float4 ws[16];

#pragma unroll
        for (int i = 0; i < 32; i++) xs[i] = xg[(size_t)i * 128u];
#pragma unroll
        for (int j = 0; j < 16; j++) ws[j] = wq[j];

        for (int c = -1; c < NCHUNK; c++) {
            if (c + 1 < NCHUNK) {
                char* sb = smem + ((c + 1) & 1) * STAGE_B;
#pragma unroll
                for (int hb2 = 0; hb2 < 2; hb2++) {
                    uint32_t ah[16], al[16], wh[16], wl[16];
#pragma unroll
                    for (int q = 0; q < 16; q++)
                        split2(xs[hb2 * 16 + q].x, xs[hb2 * 16 + q].y, ah[q], al[q]);
#pragma unroll
                    for (int j = 0; j < 8; j++) {
                        split2(ws[hb2 * 8 + j].x, ws[hb2 * 8 + j].y, wh[2*j],   wl[2*j]);
                        split2(ws[hb2 * 8 + j].z, ws[hb2 * 8 + j].w, wh[2*j+1], wl[2*j+1]);
                    }
#pragma unroll
                    for (int j = 0; j < 4; j++) {
                        uint32_t off = (uint32_t)((hb2 * 64 + j * 16) ^ xp7);
                        *(uint4*)(sb + rowA + off) =
                            make_uint4(ah[4*j], ah[4*j+1], ah[4*j+2], ah[4*j+3]);
                        *(uint4*)(sb + rowA + 128u + off) =
                            make_uint4(al[4*j], al[4*j+1], al[4*j+2], al[4*j+3]);
                        *(uint4*)(sb + rowB + off) =
                            make_uint4(wh[4*j], wh[4*j+1], wh[4*j+2], wh[4*j+3]);
                        *(uint4*)(sb + rowB + 128u + off) =
                            make_uint4(wl[4*j], wl[4*j+1], wl[4*j+2], wl[4*j+3]);
                    }
                }
                if (c + 2 < NCHUNK) {
                    const float2* xc = xg + (size_t)(c + 2) * 4096u;
#pragma unroll
                    for (int i = 0; i < 32; i++) xs[i] = xc[(size_t)i * 128u];
#pragma unroll
                    for (int j = 0; j < 16; j++) ws[j] = wq[(c + 2) * 16 + j];
                }
            }
            __syncthreads();
        }
    }

    // ---- signal this k-slice done ------------------------------------------
    __syncthreads();
    if (t == 0) {
        __threadfence();
        atomicAdd(&g_cnt[b], 1);
    }
}

// ---------------------------------------------------------------------------
// Kernel 2 — PDL-overlapped: one CTA per batch; spin, then gate 128 rows.
// ---------------------------------------------------------------------------
__global__ void __launch_bounds__(256) gate_epilogue_spin(
    const float* __restrict__ bm,
    const float* __restrict__ bn,
    float* __restrict__ out)
{
    const int t = threadIdx.x;
    const int w = t >> 5;
    const int l = t & 31;
    const int b = blockIdx.x;

    __shared__ int s_go;
    if (t == 0) {
        while (atomicAdd(&g_cnt[b], 0) < KSPLIT) __nanosleep(128);
        __threadfence();          // acquire partials
        g_cnt[b] = 0;             // reset for next graph replay
        s_go = 1;
    }
    __syncthreads();
    (void)s_go;

    // 8 warps x 16 rows, processed 2 rows at a time (MLP 8)
    for (int it = 0; it < 8; it++) {
        const int row0 = b * 128 + w * 16 + it * 2;

        float4 v[2][4];
#pragma unroll
        for (int r = 0; r < 2; r++) {
            const float4* pg = (const float4*)g_partial + (size_t)(row0 + r) * 32 + l;
#pragma unroll
            for (int kq = 0; kq < 4; kq++)
                v[r][kq] = pg[(size_t)kq * ROWS * 32];
        }

        float4 bbm, bbn;
        if (l < 16) bbm = ((const float4*)bm)[l];
        else        bbn = ((const float4*)bn)[l - 16];

#pragma unroll
        for (int r = 0; r < 2; r++) {
            float4 s;
            s.x = (v[r][0].x + v[r][1].x) + (v[r][2].x + v[r][3].x);
            s.y = (v[r][0].y + v[r][1].y) + (v[r][2].y + v[r][3].y);
            s.z = (v[r][0].z + v[r][1].z) + (v[r][2].z + v[r][3].z);
            s.w = (v[r][0].w + v[r][1].w) + (v[r][2].w + v[r][3].w);

            if (l < 16) {
                s.x += bbm.x; s.y += bbm.y; s.z += bbm.z; s.w += bbm.w;
            } else {
                s.x = softplus_f(s.x + bbn.x);
                s.y = softplus_f(s.y + bbn.y);
                s.z = softplus_f(s.z + bbn.z);
                s.w = softplus_f(s.w + bbn.w);
            }
            float n0 = __shfl_down_sync(0xffffffffu, s.x, 16);
            float n1 = __shfl_down_sync(0xffffffffu, s.y, 16);
            float n2 = __shfl_down_sync(0xffffffffu, s.z, 16);
            float n3 = __shfl_down_sync(0xffffffffu, s.w, 16);

            float g[4] = { s.x + n0, s.y + n1, s.z + n2, s.w + n3 };

            float v1t = -3.0e38f, v2t = -3.0e38f; int i1 = -1, i2 = -1;
#pragma unroll
            for (int j = 0; j < 4; j++) {
                int idx = 4 * l + j;
                if (g[j] > v1t) { v2t = v1t; i2 = i1; v1t = g[j]; i1 = idx; }
                else if (g[j] > v2t) { v2t = g[j]; i2 = idx; }
            }
#pragma unroll
            for (int m = 8; m; m >>= 1) {
                float ov1 = __shfl_xor_sync(0xffffffffu, v1t, m);
                int   oi1 = __shfl_xor_sync(0xffffffffu, i1, m);
                float ov2 = __shfl_xor_sync(0xffffffffu, v2t, m);
                int   oi2 = __shfl_xor_sync(0xffffffffu, i2, m);
                if (ov1 > v1t) {
                    float c2 = (v1t > ov2) ? v1t : ov2;
                    int  ci2 = (v1t > ov2) ? i1 : oi2;
                    v1t = ov1; i1 = oi1; v2t = c2; i2 = ci2;
                } else if (ov1 > v2t) { v2t = ov1; i2 = oi1; }
            }

            if (l < 16) {
                float ed = expf(v2t - v1t);
                float p1 = 1.0f / (1.0f + ed);
                float p2 = ed / (1.0f + ed);
                int idx = 4 * l;
                float4 o;
                o.x = (idx     == i1) ? p1 : (idx     == i2) ? p2 : 0.0f;
                o.y = (idx + 1 == i1) ? p1 : (idx + 1 == i2) ? p2 : 0.0f;
                o.z = (idx + 2 == i1) ? p1 : (idx + 2 == i2) ? p2 : 0.0f;
                o.w = (idx + 3 == i1) ? p1 : (idx + 3 == i2) ? p2 : 0.0f;
                ((float4*)out)[(size_t)(row0 + r) * 16 + l] = o;
            }
        }
    }
}

extern "C" void kernel_launch(void* const* d_in, const int* in_sizes, int n_in,
                              void* d_out, int out_size)
{
    (void)in_sizes; (void)n_in; (void)out_size;
    const float* x  = (const float*)d_in[0];
    const float* Wm = (const float*)d_in[1];
    const float* bm = (const float*)d_in[2];
    const float* Wn = (const float*)d_in[3];
    const float* bn = (const float*)d_in[4];
    float* out = (float*)d_out;

    cudaFuncSetAttribute(gate_gemm_hmma,
                         cudaFuncAttributeMaxDynamicSharedMemorySize, SMEM_BYTES);

    dim3 grid(32, KSPLIT);
    gate_gemm_hmma<<<grid, 256, SMEM_BYTES>>>(x, Wm, Wn);

    // epilogue with programmatic dependent launch (overlaps GEMM tail)
    cudaLaunchConfig_t cfg = {};
    cfg.gridDim  = dim3(32, 1, 1);
    cfg.blockDim = dim3(256, 1, 1);
    cfg.dynamicSmemBytes = 0;
    cfg.stream = 0;
    cudaLaunchAttribute attr[1];
    attr[0].id = cudaLaunchAttributeProgrammaticStreamSerialization;
    attr[0].val.programmaticStreamSerializationAllowed = 1;
    cfg.attrs = attr;
    cfg.numAttrs = 1;
    cudaLaunchKernelEx(&cfg, gate_epilogue_spin, bm, bn, out);
}

// round 16
// speedup vs baseline: 1.1786x; 1.1786x over previous
#include <cuda_runtime.h>
#include <cstdint>

// ---------------------------------------------------------------------------
// Gate_32375463478041 — champion: R11 GEMM (byte-identical) + 1024x128 epilogue
//   logits = x_r[4096,8192] @ [Wm;Wn]^T  (3-pass bf16 split: hh + hl + lh)
//   Kernel 1: CTA tile M=128/N=128, K-split 4, KB=64 chunks (32 chunks),
//     warps 0-3 MMA (64x64), warps 4-7 producers, 2-stage ring, 1 sync/chunk.
//   Kernel 2: warp-per-row gate epilogue, 1024 blocks x 128 threads.
// ---------------------------------------------------------------------------

#define KSPLIT 4
#define ROWS   4096
#define NCHUNK 32
#define TILE_B 32768            // 128 rows x 256B
#define STAGE_B (2*TILE_B)      // A tile + B tile = 64 KiB
#define SMEM_BYTES (2*STAGE_B)  // 128 KiB double buffer

__device__ float g_partial[KSPLIT * ROWS * 128];   // 8 MiB scratch

__device__ __forceinline__ uint32_t smem_u32(const void* p) {
    uint32_t a;
    asm("{ .reg .u64 t; cvta.to.shared.u64 t, %1; cvt.u32.u64 %0, t; }"
        : "=r"(a) : "l"(p));
    return a;
}

__device__ __forceinline__ void ldsm4(uint32_t* r, uint32_t addr) {
    asm volatile("ldmatrix.sync.aligned.m8n8.x4.shared.b16 {%0,%1,%2,%3}, [%4];"
                 : "=r"(r[0]), "=r"(r[1]), "=r"(r[2]), "=r"(r[3]) : "r"(addr));
}

__device__ __forceinline__ void mma16816(float* d, const uint32_t* a, const uint32_t* b) {
    asm volatile(
        "mma.sync.aligned.m16n8k16.row.col.f32.bf16.bf16.f32 "
        "{%0,%1,%2,%3}, {%4,%5,%6,%7}, {%8,%9}, {%0,%1,%2,%3};"
        : "+f"(d[0]), "+f"(d[1]), "+f"(d[2]), "+f"(d[3])
        : "r"(a[0]), "r"(a[1]), "r"(a[2]), "r"(a[3]), "r"(b[0]), "r"(b[1]));
}

__device__ __forceinline__ void split2(float f0, float f1, uint32_t& h, uint32_t& lo) {
    asm("cvt.rn.bf16x2.f32 %0, %1, %2;" : "=r"(h) : "f"(f1), "f"(f0));
    float r0 = f0 - __uint_as_float(h << 16);
    float r1 = f1 - __uint_as_float(h & 0xffff0000u);
    asm("cvt.rn.bf16x2.f32 %0, %1, %2;" : "=r"(lo) : "f"(r1), "f"(r0));
}

// ---------------------------------------------------------------------------
__global__ void __launch_bounds__(256, 1) gate_gemm_hmma(
    const float* __restrict__ x,
    const float* __restrict__ Wm,
    const float* __restrict__ Wn)
{
    extern __shared__ char smem[];
    const uint32_t sbase = smem_u32(smem);
    const int t = threadIdx.x;
    const int w = t >> 5;
    const int l = t & 31;
    const int b  = blockIdx.x;
    const int ks = blockIdx.y;

    if (w < 4) {
        // =================== MMA warps (0-3): 64x64 tile =====================
        const int wm = w & 1;           // M half
        const int wn = w >> 1;          // N half

        const int m_add = ((l >> 3) & 1) * 8 + (l & 7);
        const int kA2   = (l >> 4) * 16;
        const int xm    = (m_add & 7) * 16;
        const int n_add = (l & 7) + ((l >> 4) << 3);
        const int kB2   = ((l >> 3) & 1) * 16;
        const int xn    = (n_add & 7) * 16;

        uint32_t aRow[4], bRow[4];
#pragma unroll
        for (int i = 0; i < 4; i++) {
            aRow[i] = (uint32_t)(wm * 64 + i * 16 + m_add) * 256u;
            bRow[i] = (uint32_t)(wn * 64 + i * 16 + n_add) * 256u + TILE_B;
        }

        float acc[4][8][4];
#pragma unroll
        for (int i = 0; i < 4; i++)
#pragma unroll
            for (int j = 0; j < 8; j++)
#pragma unroll
                for (int q = 0; q < 4; q++) acc[i][j][q] = 0.0f;

        __syncthreads();   // wait for prologue fill of buffer 0

        for (int c = 0; c < NCHUNK; c++) {
            const uint32_t sb = sbase + (uint32_t)(c & 1) * STAGE_B;
            uint32_t AH[16], AL[16], BH[16], BL[16];
#pragma unroll
            for (int kk = 0; kk < 4; kk++) {
                const int koH = kk * 32;
#pragma unroll
                for (int mt = 0; mt < 4; mt++) {
                    ldsm4(AH + 4 * mt, sb + aRow[mt] + ((koH + kA2) ^ xm));
                    ldsm4(AL + 4 * mt, sb + aRow[mt] + 128u + ((koH + kA2) ^ xm));
                }
#pragma unroll
                for (int nt = 0; nt < 4; nt++) {
                    ldsm4(BH + 4 * nt, sb + bRow[nt] + ((koH + kB2) ^ xn));
                    ldsm4(BL + 4 * nt, sb + bRow[nt] + 128u + ((koH + kB2) ^ xn));
                }
#pragma unroll
                for (int mt = 0; mt < 4; mt++)
#pragma unroll
                    for (int nj = 0; nj < 8; nj++)
                        mma16816(acc[mt][nj], AH + 4 * mt, BH + 2 * nj);
#pragma unroll
                for (int mt = 0; mt < 4; mt++)
#pragma unroll
                    for (int nj = 0; nj < 8; nj++)
                        mma16816(acc[mt][nj], AH + 4 * mt, BL + 2 * nj);
#pragma unroll
                for (int mt = 0; mt < 4; mt++)
#pragma unroll
                    for (int nj = 0; nj < 8; nj++)
                        mma16816(acc[mt][nj], AL + 4 * mt, BH + 2 * nj);
            }
            __syncthreads();
        }

        // ---- write partials ----
#pragma unroll
        for (int mt = 0; mt < 4; mt++) {
            int row = b * 128 + wm * 64 + mt * 16 + (l >> 2);
#pragma unroll
            for (int nj = 0; nj < 8; nj++) {
                int col = wn * 64 + nj * 8 + 2 * (l & 3);
                size_t idx0 = ((size_t)ks * ROWS + row) * 128 + col;
                *(float2*)(g_partial + idx0)            = make_float2(acc[mt][nj][0], acc[mt][nj][1]);
                *(float2*)(g_partial + idx0 + 8 * 128)  = make_float2(acc[mt][nj][2], acc[mt][nj][3]);
            }
        }
    } else {
        // =================== producer warps (4-7) ============================
        const int p = t - 128;
        const uint32_t rowA = (uint32_t)p * 256u;
        const uint32_t rowB = (uint32_t)p * 256u + TILE_B;
        const int xp7 = (p & 7) * 16;

        const float2* xg = (const float2*)x + (size_t)b * 524288u
                                            + (size_t)ks * 131072u + p;
        const float* wbase = (p < 64) ? (Wm + (size_t)p * 8192u)
                                      : (Wn + (size_t)(p - 64) * 8192u);
        const float4* wq = (const float4*)(wbase + ks * 2048);

        float2 xs[32]; float4 ws[16];

#pragma unroll
        for (int i = 0; i < 32; i++) xs[i] = xg[(size_t)i * 128u];
#pragma unroll
        for (int j = 0; j < 16; j++) ws[j] = wq[j];

        for (int c = -1; c < NCHUNK; c++) {
            if (c + 1 < NCHUNK) {
                char* sb = smem + ((c + 1) & 1) * STAGE_B;
#pragma unroll
                for (int hb2 = 0; hb2 < 2; hb2++) {
                    uint32_t ah[16], al[16], wh[16], wl[16];
#pragma unroll
                    for (int q = 0; q < 16; q++)
                        split2(xs[hb2 * 16 + q].x, xs[hb2 * 16 + q].y, ah[q], al[q]);
#pragma unroll
                    for (int j = 0; j < 8; j++) {
                        split2(ws[hb2 * 8 + j].x, ws[hb2 * 8 + j].y, wh[2*j],   wl[2*j]);
                        split2(ws[hb2 * 8 + j].z, ws[hb2 * 8 + j].w, wh[2*j+1], wl[2*j+1]);
                    }
#pragma unroll
                    for (int j = 0; j < 4; j++) {
                        uint32_t off = (uint32_t)((hb2 * 64 + j * 16) ^ xp7);
                        *(uint4*)(sb + rowA + off) =
                            make_uint4(ah[4*j], ah[4*j+1], ah[4*j+2], ah[4*j+3]);
                        *(uint4*)(sb + rowA + 128u + off) =
                            make_uint4(al[4*j], al[4*j+1], al[4*j+2], al[4*j+3]);
                        *(uint4*)(sb + rowB + off) =
                            make_uint4(wh[4*j], wh[4*j+1], wh[4*j+2], wh[4*j+3]);
                        *(uint4*)(sb + rowB + 128u + off) =
                            make_uint4(wl[4*j], wl[4*j+1], wl[4*j+2], wl[4*j+3]);
                    }
                }
                if (c + 2 < NCHUNK) {
                    const float2* xc = xg + (size_t)(c + 2) * 4096u;
#pragma unroll
                    for (int i = 0; i < 32; i++) xs[i] = xc[(size_t)i * 128u];
#pragma unroll
                    for (int j = 0; j < 16; j++) ws[j] = wq[(c + 2) * 16 + j];
                }
            }
            __syncthreads();
        }
    }
}

// ---------------------------------------------------------------------------
// Stage 2: warp per row, float4 loads; 1024 blocks x 128 threads.
// ---------------------------------------------------------------------------
__device__ __forceinline__ float softplus_f(float v) {
    return fmaxf(v, 0.0f) + log1pf(expf(-fabsf(v)));
}

__global__ void __launch_bounds__(128) gate_epilogue_kernel(
    const float* __restrict__ bm,
    const float* __restrict__ bn,
    float* __restrict__ out)
{
    const int row  = blockIdx.x * 4 + (threadIdx.x >> 5);
    const int lane = threadIdx.x & 31;

    const float4* pg = (const float4*)g_partial + (size_t)row * 32 + lane;
    float4 v0 = pg[0];
    float4 v1 = pg[(size_t)1 * ROWS * 32];
    float4 v2_ = pg[(size_t)2 * ROWS * 32];
    float4 v3 = pg[(size_t)3 * ROWS * 32];
    float4 s;
    s.x = (v0.x + v1.x) + (v2_.x + v3.x);
    s.y = (v0.y + v1.y) + (v2_.y + v3.y);
    s.z = (v0.z + v1.z) + (v2_.z + v3.z);
    s.w = (v0.w + v1.w) + (v2_.w + v3.w);

    if (lane < 16) {
        float4 bb = ((const float4*)bm)[lane];
        s.x += bb.x; s.y += bb.y; s.z += bb.z; s.w += bb.w;
    } else {
        float4 bb = ((const float4*)bn)[lane - 16];
        s.x = softplus_f(s.x + bb.x);
        s.y = softplus_f(s.y + bb.y);
        s.z = softplus_f(s.z + bb.z);
        s.w = softplus_f(s.w + bb.w);
    }
    // add noise (lanes 16-31) into main lanes (0-15)
    float n0 = __shfl_down_sync(0xffffffffu, s.x, 16);
    float n1 = __shfl_down_sync(0xffffffffu, s.y, 16);
    float n2 = __shfl_down_sync(0xffffffffu, s.z, 16);
    float n3 = __shfl_down_sync(0xffffffffu, s.w, 16);

    float g[4] = { s.x + n0, s.y + n1, s.z + n2, s.w + n3 };

    float v1t = -3.0e38f, v2t = -3.0e38f; int i1 = -1, i2 = -1;
#pragma unroll
    for (int j = 0; j < 4; j++) {
        int idx = 4 * lane + j;
        if (g[j] > v1t) { v2t = v1t; i2 = i1; v1t = g[j]; i1 = idx; }
        else if (g[j] > v2t) { v2t = g[j]; i2 = idx; }
    }
#pragma unroll
    for (int m = 8; m; m >>= 1) {
        float ov1 = __shfl_xor_sync(0xffffffffu, v1t, m);
        int   oi1 = __shfl_xor_sync(0xffffffffu, i1, m);
        float ov2 = __shfl_xor_sync(0xffffffffu, v2t, m);
        int   oi2 = __shfl_xor_sync(0xffffffffu, i2, m);
        if (ov1 > v1t) {
            float c2 = (v1t > ov2) ? v1t : ov2;
            int  ci2 = (v1t > ov2) ? i1 : oi2;
            v1t = ov1; i1 = oi1; v2t = c2; i2 = ci2;
        } else if (ov1 > v2t) { v2t = ov1; i2 = oi1; }
    }

    if (lane < 16) {
        float ed = expf(v2t - v1t);
        float p1 = 1.0f / (1.0f + ed);
        float p2 = ed / (1.0f + ed);
        int idx = 4 * lane;
        float4 o;
        o.x = (idx     == i1) ? p1 : (idx     == i2) ? p2 : 0.0f;
        o.y = (idx + 1 == i1) ? p1 : (idx + 1 == i2) ? p2 : 0.0f;
        o.z = (idx + 2 == i1) ? p1 : (idx + 2 == i2) ? p2 : 0.0f;
        o.w = (idx + 3 == i1) ? p1 : (idx + 3 == i2) ? p2 : 0.0f;
        ((float4*)out)[(size_t)row * 16 + lane] = o;
    }
}

extern "C" void kernel_launch(void* const* d_in, const int* in_sizes, int n_in,
                              void* d_out, int out_size)
{
    (void)in_sizes; (void)n_in; (void)out_size;
    const float* x  = (const float*)d_in[0];
    const float* Wm = (const float*)d_in[1];
    const float* bm = (const float*)d_in[2];
    const float* Wn = (const float*)d_in[3];
    const float* bn = (const float*)d_in[4];
    float* out = (float*)d_out;

    cudaFuncSetAttribute(gate_gemm_hmma,
                         cudaFuncAttributeMaxDynamicSharedMemorySize, SMEM_BYTES);

    dim3 grid(32, KSPLIT);
    gate_gemm_hmma<<<grid, 256, SMEM_BYTES>>>(x, Wm, Wn);
    gate_epilogue_kernel<<<1024, 128>>>(bm, bn, out);
}